// round 9
// baseline (speedup 1.0000x reference)
#include <cuda_runtime.h>
#include <cuda_fp16.h>
#include <cstdint>
#include <math.h>

// Problem constants
#define NB   32
#define NS   2048
#define ND   1024
#define BSR  65536      // NB*NS rows
#define T_M  256
#define T_N  128
#define T_K  32
#define NKT  32         // ND / T_K
#define NT_N 8          // 1024 / 128 N-tiles

// Device scratch (no dynamic allocation allowed)
__device__ float g_qw[NB * ND];
__device__ float g_scores_part[NT_N][BSR];
__device__ float g_ctx_part[8][NB * ND];
__device__ uint4 g_keys_h4[(size_t)BSR * ND / 8];   // keys as fp16, 128 MB
__device__ uint4 g_ua_h4[ND * ND / 8];              // Ua_w as fp16, 2 MB

// ---------------- smem layout for gemm kernel (bytes) ----------------
#define SA_S     40                        // halves per row (80B: ldmatrix conflict-free)
#define A_STAGE  (T_M * SA_S * 2)          // 20480 bytes
#define B_STAGE  (T_N * SA_S * 2)          // 10240 bytes
#define NSTAGE   4
#define OFF_A    0                         // 4 stages: 81920
#define OFF_B    (NSTAGE * A_STAGE)        // 81920; 4 stages: 40960
#define OFF_QW   (OFF_B + NSTAGE * B_STAGE)   // 122880: 128 floats
#define OFF_VA   (OFF_QW + 512)
#define OFF_SC   (OFF_VA + 512)            // 512 floats
#define SMEM_BYTES (OFF_SC + 2048)         // 125952

__device__ __forceinline__ void mma_f16(float* d, const uint32_t* a, const uint32_t* b) {
    asm volatile(
        "mma.sync.aligned.m16n8k16.row.col.f32.f16.f16.f32 "
        "{%0,%1,%2,%3}, {%4,%5,%6,%7}, {%8,%9}, {%0,%1,%2,%3};"
        : "+f"(d[0]), "+f"(d[1]), "+f"(d[2]), "+f"(d[3])
        : "r"(a[0]), "r"(a[1]), "r"(a[2]), "r"(a[3]), "r"(b[0]), "r"(b[1]));
}

__device__ __forceinline__ void ldsm_x4(uint32_t* r, uint32_t addr) {
    asm volatile("ldmatrix.sync.aligned.m8n8.x4.shared.b16 {%0,%1,%2,%3}, [%4];"
        : "=r"(r[0]), "=r"(r[1]), "=r"(r[2]), "=r"(r[3]) : "r"(addr));
}

__device__ __forceinline__ uint32_t pack2h(float x, float y) {
    __half2 h = __floats2half2_rn(x, y);
    return *(uint32_t*)&h;
}

// ---------------- Kernel A: fp32 -> fp16 converters ----------------
__global__ void cvt_kernel(const float4* __restrict__ src, uint4* __restrict__ dst) {
    size_t i = (size_t)blockIdx.x * blockDim.x + threadIdx.x;   // one uint4 = 8 halves
    float4 a = src[2 * i];
    float4 b = src[2 * i + 1];
    uint4 u;
    u.x = pack2h(a.x, a.y);
    u.y = pack2h(a.z, a.w);
    u.z = pack2h(b.x, b.y);
    u.w = pack2h(b.z, b.w);
    dst[i] = u;
}

// ---------------- Kernel 0: qW[b,n] = q[b] . Wa_w[n,:] + Wa_b[n] + Ua_b[n] ----------------
__global__ void qw_kernel(const float* __restrict__ query, const float* __restrict__ Wa_w,
                          const float* __restrict__ Wa_b, const float* __restrict__ Ua_b) {
    int b = blockIdx.x;
    int tid = threadIdx.x;                    // 128 threads
    int n = blockIdx.y * 128 + tid;
    __shared__ float4 qs[256];                // q[b] as 1024 floats
    for (int i = tid; i < 256; i += 128) {
        int k = i * 4;
        // q = concat(query[b,1,:], query[b,3,:]); query is (B,4,512)
        const float* src = (k < 512) ? (query + (size_t)b * 2048 + 512 + k)
                                     : (query + (size_t)b * 2048 + 1024 + k);
        qs[i] = *(const float4*)src;
    }
    __syncthreads();
    const float4* wr = (const float4*)(Wa_w + (size_t)n * ND);
    float acc = 0.f;
    #pragma unroll 8
    for (int i = 0; i < 256; i++) {
        float4 a = qs[i], w = wr[i];
        acc += a.x * w.x + a.y * w.y + a.z * w.z + a.w * w.w;
    }
    g_qw[b * ND + n] = acc + Wa_b[n] + Ua_b[n];
}

// ---------------- Kernel 1: fp16 mma GEMM (256x128 CTA, 8 warps of 64x64, 1 CTA/SM) ----------------
__global__ void __launch_bounds__(256, 1)
gemm_score_kernel(const float* __restrict__ Va_w) {
    extern __shared__ __align__(16) char smc[];
    float* qw_s = (float*)(smc + OFF_QW);
    float* va_s = (float*)(smc + OFF_VA);
    float* sc_s = (float*)(smc + OFF_SC);

    const __half* keys_h = (const __half*)g_keys_h4;
    const __half* ua_h   = (const __half*)g_ua_h4;

    const int tid = threadIdx.x;              // 256 threads, 8 warps
    const int wid = tid >> 5;
    const int lane = tid & 31;
    const int r = lane >> 2;                  // 0..7
    const int c = lane & 3;                   // 0..3
    const int wm = wid & 3;                   // 4 warps along M (64 rows each)
    const int wn = wid >> 2;                  // 2 warps along N (64 cols each)

    const int nt = blockIdx.x;                // N-tile (fast dim -> A reuse in L2)
    const int n0 = nt * T_N;
    const int m0 = blockIdx.y * T_M;
    const int b  = blockIdx.y >> 3;           // 8 M-tiles of 256 per batch

    const uint32_t sbase = (uint32_t)__cvta_generic_to_shared(smc);
    const uint32_t sA = sbase + OFF_A;
    const uint32_t sB = sbase + OFF_B;

    // ldmatrix per-lane offsets (bytes)
    const uint32_t a_lane_off = (uint32_t)(((lane & 15) * SA_S + ((lane >> 4) << 3)) * 2);
    const uint32_t b_lane_off = (uint32_t)(((((lane >> 4) << 3) + (lane & 7)) * SA_S
                                            + (((lane >> 3) & 1) << 3)) * 2);

    // async tile loader: A = 1024 16B-chunks, B = 512; 256 threads => 4 + 2 each
    auto load_tile = [&](int kt, int p) {
        const __half* asrc = keys_h + (size_t)m0 * ND + (size_t)kt * T_K;
        const __half* bsrc = ua_h + (size_t)n0 * ND + (size_t)kt * T_K;
        uint32_t ad = sA + p * A_STAGE;
        uint32_t bd = sB + p * B_STAGE;
        #pragma unroll
        for (int i = 0; i < 4; i++) {
            int c0 = tid + i * 256;
            int row = c0 >> 2, ch = c0 & 3;
            uint32_t off = (uint32_t)((row * SA_S + ch * 8) * 2);
            asm volatile("cp.async.cg.shared.global [%0], [%1], 16;"
                :: "r"(ad + off), "l"(asrc + (size_t)row * ND + ch * 8));
        }
        #pragma unroll
        for (int i = 0; i < 2; i++) {
            int c0 = tid + i * 256;
            int row = c0 >> 2, ch = c0 & 3;
            uint32_t off = (uint32_t)((row * SA_S + ch * 8) * 2);
            asm volatile("cp.async.cg.shared.global [%0], [%1], 16;"
                :: "r"(bd + off), "l"(bsrc + (size_t)row * ND + ch * 8));
        }
        asm volatile("cp.async.commit_group;");
    };

    load_tile(0, 0);
    load_tile(1, 1);
    load_tile(2, 2);

    for (int j = tid; j < T_N; j += 256) {
        qw_s[j] = g_qw[b * ND + n0 + j];
        va_s[j] = Va_w[n0 + j];
    }

    float acc[4][8][4];
    #pragma unroll
    for (int im = 0; im < 4; im++)
        #pragma unroll
        for (int in = 0; in < 8; in++)
            #pragma unroll
            for (int k = 0; k < 4; k++) acc[im][in][k] = 0.f;

    int p = 0;
    for (int kt = 0; kt < NKT; kt++) {
        if (kt + 2 < NKT)      { asm volatile("cp.async.wait_group 2;"); }
        else if (kt + 1 < NKT) { asm volatile("cp.async.wait_group 1;"); }
        else                   { asm volatile("cp.async.wait_group 0;"); }
        __syncthreads();      // prev compute on recycled stage done + tile kt visible
        if (kt + 3 < NKT) {
            int pn = p + 3; if (pn >= NSTAGE) pn -= NSTAGE;
            load_tile(kt + 3, pn);
        }

        const uint32_t ap = sA + p * A_STAGE + wm * (64 * SA_S * 2) + a_lane_off;
        const uint32_t bp = sB + p * B_STAGE + wn * (64 * SA_S * 2) + b_lane_off;

        uint32_t afr[2][4][4], bfr[2][4][4];
        #pragma unroll
        for (int ks = 0; ks < 2; ks++) {
            const uint32_t ko = ks * 32;      // 16 halves
            #pragma unroll
            for (int im = 0; im < 4; im++)
                ldsm_x4(afr[ks][im], ap + im * (16 * SA_S * 2) + ko);
            #pragma unroll
            for (int ip = 0; ip < 4; ip++)
                ldsm_x4(bfr[ks][ip], bp + ip * (16 * SA_S * 2) + ko);
        }
        #pragma unroll
        for (int ks = 0; ks < 2; ks++) {
            #pragma unroll
            for (int in = 0; in < 8; in++) {
                const uint32_t* bb = &bfr[ks][in >> 1][(in & 1) * 2];
                #pragma unroll
                for (int im = 0; im < 4; im++)
                    mma_f16(acc[im][in], afr[ks][im], bb);
            }
        }
        p++; if (p == NSTAGE) p = 0;
    }

    // Epilogue: score_part[m] = sum_n Va[n] * tanh(acc[m][n] + qw[n]) over this CTA's 128 n
    #pragma unroll
    for (int im = 0; im < 4; im++) {
        float rs0 = 0.f, rs1 = 0.f;
        #pragma unroll
        for (int in = 0; in < 8; in++) {
            int col0 = wn * 64 + in * 8 + 2 * c;
            float v0 = va_s[col0],     q0 = qw_s[col0];
            float v1 = va_s[col0 + 1], q1 = qw_s[col0 + 1];
            rs0 += v0 * tanhf(acc[im][in][0] + q0) + v1 * tanhf(acc[im][in][1] + q1);
            rs1 += v0 * tanhf(acc[im][in][2] + q0) + v1 * tanhf(acc[im][in][3] + q1);
        }
        // reduce the 4 lanes sharing each row (lane^1, lane^2 stay in the quad)
        rs0 += __shfl_xor_sync(0xffffffffu, rs0, 1);
        rs0 += __shfl_xor_sync(0xffffffffu, rs0, 2);
        rs1 += __shfl_xor_sync(0xffffffffu, rs1, 1);
        rs1 += __shfl_xor_sync(0xffffffffu, rs1, 2);
        if (c == 0) {
            int rowb = wm * 64 + im * 16 + r;
            sc_s[wn * 256 + rowb] = rs0;
            sc_s[wn * 256 + rowb + 8] = rs1;
        }
    }
    __syncthreads();
    g_scores_part[nt][m0 + tid] = sc_s[tid] + sc_s[256 + tid];
}

// ---------------- Kernel 2: softmax over S per batch, writes weights output ----------------
__global__ void softmax_kernel(float* __restrict__ wts) {
    int b = blockIdx.x;
    int tid = threadIdx.x;                    // 256 threads
    __shared__ float red[8];
    float v[8];
    float mx = -1e30f;
    #pragma unroll
    for (int i = 0; i < 8; i++) {
        int s = tid + i * 256;
        float x = 0.f;
        #pragma unroll
        for (int t = 0; t < NT_N; t++) x += g_scores_part[t][b * NS + s];
        v[i] = x;
        mx = fmaxf(mx, x);
    }
    #pragma unroll
    for (int o = 16; o; o >>= 1) mx = fmaxf(mx, __shfl_xor_sync(0xffffffffu, mx, o));
    if ((tid & 31) == 0) red[tid >> 5] = mx;
    __syncthreads();
    float bm = red[0];
    #pragma unroll
    for (int i = 1; i < 8; i++) bm = fmaxf(bm, red[i]);
    __syncthreads();
    float sum = 0.f;
    #pragma unroll
    for (int i = 0; i < 8; i++) { v[i] = __expf(v[i] - bm); sum += v[i]; }
    #pragma unroll
    for (int o = 16; o; o >>= 1) sum += __shfl_xor_sync(0xffffffffu, sum, o);
    if ((tid & 31) == 0) red[tid >> 5] = sum;
    __syncthreads();
    float bs = 0.f;
    #pragma unroll
    for (int i = 0; i < 8; i++) bs += red[i];
    float inv = 1.0f / bs;
    #pragma unroll
    for (int i = 0; i < 8; i++) wts[b * NS + tid + i * 256] = v[i] * inv;
}

// ---------------- Kernel 3: context partials from fp16 keys (halved traffic) ----------------
__global__ void ctx_part_kernel(const float* __restrict__ wts) {
    const __half* keys_h = (const __half*)g_keys_h4;
    int b = blockIdx.x;
    int d = blockIdx.y * 128 + threadIdx.x;
    int z = blockIdx.z;
    int s0 = z * 256;
    __shared__ float ws[256];
    for (int i = threadIdx.x; i < 256; i += 128) ws[i] = wts[b * NS + s0 + i];
    __syncthreads();
    const __half* kp = keys_h + ((size_t)(b * NS + s0)) * ND + d;
    float acc = 0.f;
    #pragma unroll 8
    for (int s = 0; s < 256; s++) acc += ws[s] * __half2float(kp[(size_t)s * ND]);
    g_ctx_part[z][b * ND + d] = acc;
}

// ---------------- Kernel 4: reduce context partials -> output ----------------
__global__ void ctx_reduce_kernel(float* __restrict__ ctx) {
    int b = blockIdx.x;
    int d = threadIdx.x;                      // 1024 threads
    float a = 0.f;
    #pragma unroll
    for (int z = 0; z < 8; z++) a += g_ctx_part[z][b * ND + d];
    ctx[b * ND + d] = a;
}

// ---------------- launch ----------------
extern "C" void kernel_launch(void* const* d_in, const int* in_sizes, int n_in,
                              void* d_out, int out_size) {
    const float* query = (const float*)d_in[0];
    const float* keys  = (const float*)d_in[1];
    const float* Wa_w  = (const float*)d_in[2];
    const float* Wa_b  = (const float*)d_in[3];
    const float* Ua_w  = (const float*)d_in[4];
    const float* Ua_b  = (const float*)d_in[5];
    const float* Va_w  = (const float*)d_in[6];
    // Va_b (d_in[7]) cancels in softmax; scores are not an output.

    float* out = (float*)d_out;
    float* ctx = out;                                  // (B,1,2H) = 32768 floats
    float* wts = (out_size >= NB * ND + NB * NS) ? out + NB * ND : out;  // (B,1,S)

    uint4* keys_h4;  cudaGetSymbolAddress((void**)&keys_h4, g_keys_h4);
    uint4* ua_h4;    cudaGetSymbolAddress((void**)&ua_h4, g_ua_h4);

    cudaFuncSetAttribute(gemm_score_kernel, cudaFuncAttributeMaxDynamicSharedMemorySize, SMEM_BYTES);

    cvt_kernel<<<(size_t)BSR * ND / 8 / 256, 256>>>((const float4*)keys, keys_h4);
    cvt_kernel<<<ND * ND / 8 / 256, 256>>>((const float4*)Ua_w, ua_h4);
    qw_kernel<<<dim3(NB, 8), 128>>>(query, Wa_w, Wa_b, Ua_b);
    gemm_score_kernel<<<dim3(NT_N, BSR / T_M), 256, SMEM_BYTES>>>(Va_w);
    softmax_kernel<<<NB, 256>>>(wts);
    ctx_part_kernel<<<dim3(NB, 8, 8), 128>>>(wts);
    ctx_reduce_kernel<<<NB, 1024>>>(ctx);
}

// round 10
// speedup vs baseline: 1.2164x; 1.2164x over previous
#include <cuda_runtime.h>
#include <cuda_fp16.h>
#include <cstdint>
#include <math.h>

// Problem constants
#define NB   32
#define NS   2048
#define ND   1024
#define BSR  65536      // NB*NS rows
#define T_M  128
#define T_N  128
#define T_K  64
#define NKT  16         // ND / T_K
#define NT_N 8          // 1024 / 128 N-tiles

// Device scratch (no dynamic allocation allowed)
__device__ float g_qw[NB * ND];
__device__ float g_scores_part[NT_N][BSR];
__device__ float g_ctx_part[8][NB * ND];
__device__ uint4 g_keys_h4[(size_t)BSR * ND / 8];   // keys as fp16, 128 MB
__device__ uint4 g_ua_h4[ND * ND / 8];              // Ua_w as fp16, 2 MB

// ---------------- smem layout for gemm kernel (bytes) ----------------
#define SA_S     72                        // halves per row (144B: ldmatrix conflict-free)
#define STAGE_B  (T_M * SA_S * 2)          // 18432 bytes per stage per matrix
#define NSTAGE   2
#define OFF_A    0                         // 2 stages: 36864
#define OFF_B    (NSTAGE * STAGE_B)        // 36864; 2 stages: 36864
#define OFF_QW   (2 * NSTAGE * STAGE_B)    // 73728: 128 floats
#define OFF_VA   (OFF_QW + 512)
#define OFF_SC   (OFF_VA + 512)            // 256 floats
#define SMEM_BYTES (OFF_SC + 1024)         // 75776

__device__ __forceinline__ void mma_f16(float* d, const uint32_t* a, const uint32_t* b) {
    asm volatile(
        "mma.sync.aligned.m16n8k16.row.col.f32.f16.f16.f32 "
        "{%0,%1,%2,%3}, {%4,%5,%6,%7}, {%8,%9}, {%0,%1,%2,%3};"
        : "+f"(d[0]), "+f"(d[1]), "+f"(d[2]), "+f"(d[3])
        : "r"(a[0]), "r"(a[1]), "r"(a[2]), "r"(a[3]), "r"(b[0]), "r"(b[1]));
}

__device__ __forceinline__ void ldsm_x4(uint32_t* r, uint32_t addr) {
    asm volatile("ldmatrix.sync.aligned.m8n8.x4.shared.b16 {%0,%1,%2,%3}, [%4];"
        : "=r"(r[0]), "=r"(r[1]), "=r"(r[2]), "=r"(r[3]) : "r"(addr));
}

__device__ __forceinline__ uint32_t pack2h(float x, float y) {
    __half2 h = __floats2half2_rn(x, y);
    return *(uint32_t*)&h;
}

// ---------------- Kernel A: fp32 -> fp16 converters ----------------
__global__ void cvt_kernel(const float4* __restrict__ src, uint4* __restrict__ dst) {
    size_t i = (size_t)blockIdx.x * blockDim.x + threadIdx.x;   // one uint4 = 8 halves
    float4 a = src[2 * i];
    float4 b = src[2 * i + 1];
    uint4 u;
    u.x = pack2h(a.x, a.y);
    u.y = pack2h(a.z, a.w);
    u.z = pack2h(b.x, b.y);
    u.w = pack2h(b.z, b.w);
    dst[i] = u;
}

// ---------------- Kernel 0: qW[b,n] = q[b] . Wa_w[n,:] + Wa_b[n] + Ua_b[n] ----------------
__global__ void qw_kernel(const float* __restrict__ query, const float* __restrict__ Wa_w,
                          const float* __restrict__ Wa_b, const float* __restrict__ Ua_b) {
    int b = blockIdx.x;
    int tid = threadIdx.x;                    // 128 threads
    int n = blockIdx.y * 128 + tid;
    __shared__ float4 qs[256];                // q[b] as 1024 floats
    for (int i = tid; i < 256; i += 128) {
        int k = i * 4;
        // q = concat(query[b,1,:], query[b,3,:]); query is (B,4,512)
        const float* src = (k < 512) ? (query + (size_t)b * 2048 + 512 + k)
                                     : (query + (size_t)b * 2048 + 1024 + k);
        qs[i] = *(const float4*)src;
    }
    __syncthreads();
    const float4* wr = (const float4*)(Wa_w + (size_t)n * ND);
    float acc = 0.f;
    #pragma unroll 8
    for (int i = 0; i < 256; i++) {
        float4 a = qs[i], w = wr[i];
        acc += a.x * w.x + a.y * w.y + a.z * w.z + a.w * w.w;
    }
    g_qw[b * ND + n] = acc + Wa_b[n] + Ua_b[n];
}

// ---------------- Kernel 1: fp16 mma GEMM (128x128 CTA, 4 warps of 64x64, 2 CTA/SM, T_K=64) ----------------
__global__ void __launch_bounds__(128, 2)
gemm_score_kernel(const float* __restrict__ Va_w) {
    extern __shared__ __align__(16) char smc[];
    float* qw_s = (float*)(smc + OFF_QW);
    float* va_s = (float*)(smc + OFF_VA);
    float* sc_s = (float*)(smc + OFF_SC);

    const __half* keys_h = (const __half*)g_keys_h4;
    const __half* ua_h   = (const __half*)g_ua_h4;

    const int tid = threadIdx.x;              // 128 threads, 4 warps
    const int wid = tid >> 5;
    const int lane = tid & 31;
    const int r = lane >> 2;                  // 0..7
    const int c = lane & 3;                   // 0..3
    const int wm = wid & 1;                   // 2 warps along M (64 rows each)
    const int wn = wid >> 1;                  // 2 warps along N (64 cols each)

    const int nt = blockIdx.x;                // N-tile (fast dim -> A reuse in L2)
    const int n0 = nt * T_N;
    const int m0 = blockIdx.y * T_M;
    const int b  = blockIdx.y >> 4;           // 16 M-tiles of 128 per batch

    const uint32_t sbase = (uint32_t)__cvta_generic_to_shared(smc);
    const uint32_t sA = sbase + OFF_A;
    const uint32_t sB = sbase + OFF_B;

    // ldmatrix per-lane offsets (bytes)
    const uint32_t a_lane_off = (uint32_t)(((lane & 15) * SA_S + ((lane >> 4) << 3)) * 2);
    const uint32_t b_lane_off = (uint32_t)(((((lane >> 4) << 3) + (lane & 7)) * SA_S
                                            + (((lane >> 3) & 1) << 3)) * 2);

    // async tile loader: 1024 16B-chunks per matrix (8 per row), 128 threads => 8+8 each
    auto load_tile = [&](int kt, int p) {
        const __half* asrc = keys_h + (size_t)m0 * ND + (size_t)kt * T_K;
        const __half* bsrc = ua_h + (size_t)n0 * ND + (size_t)kt * T_K;
        uint32_t ad = sA + p * STAGE_B;
        uint32_t bd = sB + p * STAGE_B;
        #pragma unroll
        for (int i = 0; i < 8; i++) {
            int c0 = tid + i * 128;
            int row = c0 >> 3, ch = c0 & 7;
            uint32_t off = (uint32_t)((row * SA_S + ch * 8) * 2);
            asm volatile("cp.async.cg.shared.global [%0], [%1], 16;"
                :: "r"(ad + off), "l"(asrc + (size_t)row * ND + ch * 8));
            asm volatile("cp.async.cg.shared.global [%0], [%1], 16;"
                :: "r"(bd + off), "l"(bsrc + (size_t)row * ND + ch * 8));
        }
        asm volatile("cp.async.commit_group;");
    };

    load_tile(0, 0);

    for (int j = tid; j < T_N; j += 128) {
        qw_s[j] = g_qw[b * ND + n0 + j];
        va_s[j] = Va_w[n0 + j];
    }

    float acc[4][8][4];
    #pragma unroll
    for (int im = 0; im < 4; im++)
        #pragma unroll
        for (int in = 0; in < 8; in++)
            #pragma unroll
            for (int k = 0; k < 4; k++) acc[im][in][k] = 0.f;

    for (int kt = 0; kt < NKT; kt++) {
        const int p = kt & 1;
        asm volatile("cp.async.wait_group 0;");   // tile kt landed
        __syncthreads();                          // all warps past compute kt-1 (buffer 1-p)
        if (kt + 1 < NKT)
            load_tile(kt + 1, 1 - p);             // prefetch overlaps compute below

        const uint32_t ap = sA + p * STAGE_B + wm * (64 * SA_S * 2) + a_lane_off;
        const uint32_t bp = sB + p * STAGE_B + wn * (64 * SA_S * 2) + b_lane_off;

        #pragma unroll
        for (int ks = 0; ks < 4; ks++) {          // 4 k16 steps per 64-K tile
            const uint32_t ko = ks * 32;          // 16 halves
            uint32_t afr[4][4], bfr[4][4];
            #pragma unroll
            for (int im = 0; im < 4; im++)
                ldsm_x4(afr[im], ap + im * (16 * SA_S * 2) + ko);
            #pragma unroll
            for (int ip = 0; ip < 4; ip++)
                ldsm_x4(bfr[ip], bp + ip * (16 * SA_S * 2) + ko);
            #pragma unroll
            for (int in = 0; in < 8; in++) {
                const uint32_t* bb = &bfr[in >> 1][(in & 1) * 2];
                #pragma unroll
                for (int im = 0; im < 4; im++)
                    mma_f16(acc[im][in], afr[im], bb);
            }
        }
    }

    // Epilogue: score_part[m] = sum_n Va[n] * tanh(acc[m][n] + qw[n]) over this CTA's 128 n
    #pragma unroll
    for (int im = 0; im < 4; im++) {
        float rs0 = 0.f, rs1 = 0.f;
        #pragma unroll
        for (int in = 0; in < 8; in++) {
            int col0 = wn * 64 + in * 8 + 2 * c;
            float v0 = va_s[col0],     q0 = qw_s[col0];
            float v1 = va_s[col0 + 1], q1 = qw_s[col0 + 1];
            rs0 += v0 * tanhf(acc[im][in][0] + q0) + v1 * tanhf(acc[im][in][1] + q1);
            rs1 += v0 * tanhf(acc[im][in][2] + q0) + v1 * tanhf(acc[im][in][3] + q1);
        }
        // reduce the 4 lanes sharing each row (lane^1, lane^2 stay in the quad)
        rs0 += __shfl_xor_sync(0xffffffffu, rs0, 1);
        rs0 += __shfl_xor_sync(0xffffffffu, rs0, 2);
        rs1 += __shfl_xor_sync(0xffffffffu, rs1, 1);
        rs1 += __shfl_xor_sync(0xffffffffu, rs1, 2);
        if (c == 0) {
            int rowb = wm * 64 + im * 16 + r;
            sc_s[wn * 128 + rowb] = rs0;
            sc_s[wn * 128 + rowb + 8] = rs1;
        }
    }
    __syncthreads();
    g_scores_part[nt][m0 + tid] = sc_s[tid] + sc_s[128 + tid];
}

// ---------------- Kernel 2: softmax over S per batch, writes weights output ----------------
__global__ void softmax_kernel(float* __restrict__ wts) {
    int b = blockIdx.x;
    int tid = threadIdx.x;                    // 256 threads
    __shared__ float red[8];
    float v[8];
    float mx = -1e30f;
    #pragma unroll
    for (int i = 0; i < 8; i++) {
        int s = tid + i * 256;
        float x = 0.f;
        #pragma unroll
        for (int t = 0; t < NT_N; t++) x += g_scores_part[t][b * NS + s];
        v[i] = x;
        mx = fmaxf(mx, x);
    }
    #pragma unroll
    for (int o = 16; o; o >>= 1) mx = fmaxf(mx, __shfl_xor_sync(0xffffffffu, mx, o));
    if ((tid & 31) == 0) red[tid >> 5] = mx;
    __syncthreads();
    float bm = red[0];
    #pragma unroll
    for (int i = 1; i < 8; i++) bm = fmaxf(bm, red[i]);
    __syncthreads();
    float sum = 0.f;
    #pragma unroll
    for (int i = 0; i < 8; i++) { v[i] = __expf(v[i] - bm); sum += v[i]; }
    #pragma unroll
    for (int o = 16; o; o >>= 1) sum += __shfl_xor_sync(0xffffffffu, sum, o);
    if ((tid & 31) == 0) red[tid >> 5] = sum;
    __syncthreads();
    float bs = 0.f;
    #pragma unroll
    for (int i = 0; i < 8; i++) bs += red[i];
    float inv = 1.0f / bs;
    #pragma unroll
    for (int i = 0; i < 8; i++) wts[b * NS + tid + i * 256] = v[i] * inv;
}

// ---------------- Kernel 3: context partials from fp16 keys (halved traffic) ----------------
__global__ void ctx_part_kernel(const float* __restrict__ wts) {
    const __half* keys_h = (const __half*)g_keys_h4;
    int b = blockIdx.x;
    int d = blockIdx.y * 128 + threadIdx.x;
    int z = blockIdx.z;
    int s0 = z * 256;
    __shared__ float ws[256];
    for (int i = threadIdx.x; i < 256; i += 128) ws[i] = wts[b * NS + s0 + i];
    __syncthreads();
    const __half* kp = keys_h + ((size_t)(b * NS + s0)) * ND + d;
    float acc = 0.f;
    #pragma unroll 8
    for (int s = 0; s < 256; s++) acc += ws[s] * __half2float(kp[(size_t)s * ND]);
    g_ctx_part[z][b * ND + d] = acc;
}

// ---------------- Kernel 4: reduce context partials -> output ----------------
__global__ void ctx_reduce_kernel(float* __restrict__ ctx) {
    int b = blockIdx.x;
    int d = threadIdx.x;                      // 1024 threads
    float a = 0.f;
    #pragma unroll
    for (int z = 0; z < 8; z++) a += g_ctx_part[z][b * ND + d];
    ctx[b * ND + d] = a;
}

// ---------------- launch ----------------
extern "C" void kernel_launch(void* const* d_in, const int* in_sizes, int n_in,
                              void* d_out, int out_size) {
    const float* query = (const float*)d_in[0];
    const float* keys  = (const float*)d_in[1];
    const float* Wa_w  = (const float*)d_in[2];
    const float* Wa_b  = (const float*)d_in[3];
    const float* Ua_w  = (const float*)d_in[4];
    const float* Ua_b  = (const float*)d_in[5];
    const float* Va_w  = (const float*)d_in[6];
    // Va_b (d_in[7]) cancels in softmax; scores are not an output.

    float* out = (float*)d_out;
    float* ctx = out;                                  // (B,1,2H) = 32768 floats
    float* wts = (out_size >= NB * ND + NB * NS) ? out + NB * ND : out;  // (B,1,S)

    uint4* keys_h4;  cudaGetSymbolAddress((void**)&keys_h4, g_keys_h4);
    uint4* ua_h4;    cudaGetSymbolAddress((void**)&ua_h4, g_ua_h4);

    cudaFuncSetAttribute(gemm_score_kernel, cudaFuncAttributeMaxDynamicSharedMemorySize, SMEM_BYTES);

    cvt_kernel<<<(size_t)BSR * ND / 8 / 256, 256>>>((const float4*)keys, keys_h4);
    cvt_kernel<<<ND * ND / 8 / 256, 256>>>((const float4*)Ua_w, ua_h4);
    qw_kernel<<<dim3(NB, 8), 128>>>(query, Wa_w, Wa_b, Ua_b);
    gemm_score_kernel<<<dim3(NT_N, BSR / T_M), 128, SMEM_BYTES>>>(Va_w);
    softmax_kernel<<<NB, 256>>>(wts);
    ctx_part_kernel<<<dim3(NB, 8, 8), 128>>>(wts);
    ctx_reduce_kernel<<<NB, 1024>>>(ctx);
}

// round 12
// speedup vs baseline: 1.3144x; 1.0806x over previous
#include <cuda_runtime.h>
#include <cuda_fp16.h>
#include <cstdint>
#include <math.h>

// Problem constants
#define NB   32
#define NS   2048
#define ND   1024
#define BSR  65536      // NB*NS rows
#define T_M  128
#define T_N  128
#define T_K  32
#define NKT  32         // ND / T_K
#define NT_N 8          // 1024 / 128 N-tiles

// Device scratch (no dynamic allocation allowed)
__device__ float g_qw[NB * ND];
__device__ float g_scores_part[NT_N][BSR];
__device__ float g_ctx_part[8][NB * ND];
__device__ uint4 g_keys_h4[(size_t)BSR * ND / 8];   // keys as fp16, 128 MB
__device__ uint4 g_ua_h4[ND * ND / 8];              // Ua_w as fp16, 2 MB

// ---------------- smem layout for gemm kernel (bytes) ----------------
// Per warp per stage: A 64x32 fp16 (4KB, 64B rows, XOR-swizzled) + B 64x32 (4KB)
#define WS_BYTES 8192                      // per warp per stage (A + B)
#define NSTAGE   3
#define OFF_QW   (NSTAGE * 4 * WS_BYTES)   // 98304: 128 floats
#define OFF_VA   (OFF_QW + 512)
#define OFF_SC   (OFF_VA + 512)            // 256 floats
#define SMEM_BYTES (OFF_SC + 1024)         // 100352

__device__ __forceinline__ void mma_f16(float* d, const uint32_t* a, const uint32_t* b) {
    asm volatile(
        "mma.sync.aligned.m16n8k16.row.col.f32.f16.f16.f32 "
        "{%0,%1,%2,%3}, {%4,%5,%6,%7}, {%8,%9}, {%0,%1,%2,%3};"
        : "+f"(d[0]), "+f"(d[1]), "+f"(d[2]), "+f"(d[3])
        : "r"(a[0]), "r"(a[1]), "r"(a[2]), "r"(a[3]), "r"(b[0]), "r"(b[1]));
}

__device__ __forceinline__ void ldsm_x4(uint32_t* r, uint32_t addr) {
    asm volatile("ldmatrix.sync.aligned.m8n8.x4.shared.b16 {%0,%1,%2,%3}, [%4];"
        : "=r"(r[0]), "=r"(r[1]), "=r"(r[2]), "=r"(r[3]) : "r"(addr));
}

__device__ __forceinline__ uint32_t pack2h(float x, float y) {
    __half2 h = __floats2half2_rn(x, y);
    return *(uint32_t*)&h;
}

// ---------------- Kernel A: fp32 -> fp16 converters ----------------
__global__ void cvt_kernel(const float4* __restrict__ src, uint4* __restrict__ dst) {
    size_t i = (size_t)blockIdx.x * blockDim.x + threadIdx.x;   // one uint4 = 8 halves
    float4 a = src[2 * i];
    float4 b = src[2 * i + 1];
    uint4 u;
    u.x = pack2h(a.x, a.y);
    u.y = pack2h(a.z, a.w);
    u.z = pack2h(b.x, b.y);
    u.w = pack2h(b.z, b.w);
    dst[i] = u;
}

// ---------------- Kernel 0: qW[b,n] = q[b] . Wa_w[n,:] + Wa_b[n] + Ua_b[n] ----------------
__global__ void qw_kernel(const float* __restrict__ query, const float* __restrict__ Wa_w,
                          const float* __restrict__ Wa_b, const float* __restrict__ Ua_b) {
    int b = blockIdx.x;
    int tid = threadIdx.x;                    // 128 threads
    int n = blockIdx.y * 128 + tid;
    __shared__ float4 qs[256];                // q[b] as 1024 floats
    for (int i = tid; i < 256; i += 128) {
        int k = i * 4;
        // q = concat(query[b,1,:], query[b,3,:]); query is (B,4,512)
        const float* src = (k < 512) ? (query + (size_t)b * 2048 + 512 + k)
                                     : (query + (size_t)b * 2048 + 1024 + k);
        qs[i] = *(const float4*)src;
    }
    __syncthreads();
    const float4* wr = (const float4*)(Wa_w + (size_t)n * ND);
    float acc = 0.f;
    #pragma unroll 8
    for (int i = 0; i < 256; i++) {
        float4 a = qs[i], w = wr[i];
        acc += a.x * w.x + a.y * w.y + a.z * w.z + a.w * w.w;
    }
    g_qw[b * ND + n] = acc + Wa_b[n] + Ua_b[n];
}

// ---------------- Kernel 1: fp16 mma GEMM, warp-autonomous pipeline ----------------
// 128x128 CTA, 4 warps of 64x64, 2 CTA/SM. Each warp loads its OWN A/B stripes;
// NO cta-wide barriers in the mainloop (cp.async.wait_group + __syncwarp only).
__global__ void __launch_bounds__(128, 2)
gemm_score_kernel(const float* __restrict__ Va_w) {
    extern __shared__ __align__(16) char smc[];
    float* qw_s = (float*)(smc + OFF_QW);
    float* va_s = (float*)(smc + OFF_VA);
    float* sc_s = (float*)(smc + OFF_SC);

    const __half* keys_h = (const __half*)g_keys_h4;
    const __half* ua_h   = (const __half*)g_ua_h4;

    const int tid = threadIdx.x;              // 128 threads, 4 warps
    const int wid = tid >> 5;
    const int lane = tid & 31;
    const int r = lane >> 2;                  // 0..7
    const int c = lane & 3;                   // 0..3
    const int wm = wid & 1;                   // 2 warps along M (64 rows each)
    const int wn = wid >> 1;                  // 2 warps along N (64 cols each)

    const int nt = blockIdx.x;                // N-tile (fast dim -> A reuse in L2)
    const int n0 = nt * T_N;
    const int m0 = blockIdx.y * T_M;
    const int b  = blockIdx.y >> 4;           // 16 M-tiles of 128 per batch

    const uint32_t sbase = (uint32_t)__cvta_generic_to_shared(smc);

    // global stripe bases for this warp
    const __half* agl = keys_h + (size_t)(m0 + wm * 64) * ND;
    const __half* bgl = ua_h + (size_t)(n0 + wn * 64) * ND;

    // loader lane geometry: 256 chunks (16B) per 4KB stripe, 8 per lane
    // chunk j: row = j>>2, c0 = j&3; smem chunk = c0 ^ ((row>>1)&3)  (XOR swizzle)
    auto load_tile = [&](int kt, int s) {
        uint32_t wb = sbase + (s * 4 + wid) * WS_BYTES;
        const __half* asrc = agl + (size_t)kt * T_K;
        const __half* bsrc = bgl + (size_t)kt * T_K;
        #pragma unroll
        for (int i = 0; i < 8; i++) {
            int j = lane + i * 32;
            int row = j >> 2, c0 = j & 3;
            int ch = c0 ^ ((row >> 1) & 3);
            uint32_t doff = (uint32_t)(row * 64 + ch * 16);
            asm volatile("cp.async.cg.shared.global [%0], [%1], 16;"
                :: "r"(wb + doff), "l"(asrc + (size_t)row * ND + c0 * 8));
            asm volatile("cp.async.cg.shared.global [%0], [%1], 16;"
                :: "r"(wb + 4096 + doff), "l"(bsrc + (size_t)row * ND + c0 * 8));
        }
        asm volatile("cp.async.commit_group;");
    };

    // ldmatrix lane geometry (A-fragment): lanes 0-15 -> rows 0-15, lanes 16-31 -> k+16B
    const int frow_a = lane & 15;
    const int kh_a   = lane >> 4;
    const int sw_a   = (frow_a >> 1) & 3;
    // ldmatrix lane geometry (B-fragment): lanes {0-7,8-15,16-23,24-31} ->
    //   {n0-7/k0, n0-7/k1, n8-15/k0, n8-15/k1}
    const int frow_b = ((lane >> 4) << 3) + (lane & 7);
    const int kh_b   = (lane >> 3) & 1;
    const int sw_b   = (frow_b >> 1) & 3;     // = ((lane&7)>>1)&3

    for (int j = tid; j < T_N; j += 128) {
        qw_s[j] = g_qw[b * ND + n0 + j];
        va_s[j] = Va_w[n0 + j];
    }
    __syncthreads();                          // qw/va visible before any warp's epilogue

    load_tile(0, 0);
    load_tile(1, 1);
    load_tile(2, 2);

    float acc[4][8][4];
    #pragma unroll
    for (int im = 0; im < 4; im++)
        #pragma unroll
        for (int in = 0; in < 8; in++)
            #pragma unroll
            for (int k = 0; k < 4; k++) acc[im][in][k] = 0.f;

    for (int kt = 0; kt < NKT; kt++) {
        const int s = kt % NSTAGE;
        if (kt + 3 < NKT) { asm volatile("cp.async.wait_group 2;"); }
        else              { asm volatile("cp.async.wait_group 0;"); }
        __syncwarp();                         // make all lanes' landed copies warp-visible

        const uint32_t wb = sbase + (s * 4 + wid) * WS_BYTES;
        #pragma unroll
        for (int ks = 0; ks < 2; ks++) {
            uint32_t afr[4][4], bfr[4][4];
            #pragma unroll
            for (int im = 0; im < 4; im++) {
                uint32_t ra = wb + (uint32_t)((im * 16 + frow_a) * 64
                              + ((ks * 2 + kh_a) ^ sw_a) * 16);
                ldsm_x4(afr[im], ra);
            }
            #pragma unroll
            for (int ip = 0; ip < 4; ip++) {
                uint32_t rb = wb + 4096 + (uint32_t)((ip * 16 + frow_b) * 64
                              + ((ks * 2 + kh_b) ^ sw_b) * 16);
                ldsm_x4(bfr[ip], rb);
            }
            #pragma unroll
            for (int in = 0; in < 8; in++) {
                const uint32_t* bb = &bfr[in >> 1][(in & 1) * 2];
                #pragma unroll
                for (int im = 0; im < 4; im++)
                    mma_f16(acc[im][in], afr[im], bb);
            }
        }
        if (kt + 3 < NKT)
            load_tile(kt + 3, s);             // reuse stage s (compute on it is done)
    }

    // Epilogue: score_part[m] = sum_n Va[n] * tanh(acc[m][n] + qw[n]) over this CTA's 128 n
    #pragma unroll
    for (int im = 0; im < 4; im++) {
        float rs0 = 0.f, rs1 = 0.f;
        #pragma unroll
        for (int in = 0; in < 8; in++) {
            int col0 = wn * 64 + in * 8 + 2 * c;
            float v0 = va_s[col0],     q0 = qw_s[col0];
            float v1 = va_s[col0 + 1], q1 = qw_s[col0 + 1];
            rs0 += v0 * tanhf(acc[im][in][0] + q0) + v1 * tanhf(acc[im][in][1] + q1);
            rs1 += v0 * tanhf(acc[im][in][2] + q0) + v1 * tanhf(acc[im][in][3] + q1);
        }
        // reduce the 4 lanes sharing each row (lane^1, lane^2 stay in the quad)
        rs0 += __shfl_xor_sync(0xffffffffu, rs0, 1);
        rs0 += __shfl_xor_sync(0xffffffffu, rs0, 2);
        rs1 += __shfl_xor_sync(0xffffffffu, rs1, 1);
        rs1 += __shfl_xor_sync(0xffffffffu, rs1, 2);
        if (c == 0) {
            int rowb = wm * 64 + im * 16 + r;
            sc_s[wn * 128 + rowb] = rs0;
            sc_s[wn * 128 + rowb + 8] = rs1;
        }
    }
    __syncthreads();
    g_scores_part[nt][m0 + tid] = sc_s[tid] + sc_s[128 + tid];
}

// ---------------- Kernel 2: softmax over S per batch, writes weights output ----------------
__global__ void softmax_kernel(float* __restrict__ wts) {
    int b = blockIdx.x;
    int tid = threadIdx.x;                    // 256 threads
    __shared__ float red[8];
    float v[8];
    float mx = -1e30f;
    #pragma unroll
    for (int i = 0; i < 8; i++) {
        int s = tid + i * 256;
        float x = 0.f;
        #pragma unroll
        for (int t = 0; t < NT_N; t++) x += g_scores_part[t][b * NS + s];
        v[i] = x;
        mx = fmaxf(mx, x);
    }
    #pragma unroll
    for (int o = 16; o; o >>= 1) mx = fmaxf(mx, __shfl_xor_sync(0xffffffffu, mx, o));
    if ((tid & 31) == 0) red[tid >> 5] = mx;
    __syncthreads();
    float bm = red[0];
    #pragma unroll
    for (int i = 1; i < 8; i++) bm = fmaxf(bm, red[i]);
    __syncthreads();
    float sum = 0.f;
    #pragma unroll
    for (int i = 0; i < 8; i++) { v[i] = __expf(v[i] - bm); sum += v[i]; }
    #pragma unroll
    for (int o = 16; o; o >>= 1) sum += __shfl_xor_sync(0xffffffffu, sum, o);
    if ((tid & 31) == 0) red[tid >> 5] = sum;
    __syncthreads();
    float bs = 0.f;
    #pragma unroll
    for (int i = 0; i < 8; i++) bs += red[i];
    float inv = 1.0f / bs;
    #pragma unroll
    for (int i = 0; i < 8; i++) wts[b * NS + tid + i * 256] = v[i] * inv;
}

// ---------------- Kernel 3: context partials from fp16 keys (halved traffic) ----------------
__global__ void ctx_part_kernel(const float* __restrict__ wts) {
    const __half* keys_h = (const __half*)g_keys_h4;
    int b = blockIdx.x;
    int d = blockIdx.y * 128 + threadIdx.x;
    int z = blockIdx.z;
    int s0 = z * 256;
    __shared__ float ws[256];
    for (int i = threadIdx.x; i < 256; i += 128) ws[i] = wts[b * NS + s0 + i];
    __syncthreads();
    const __half* kp = keys_h + ((size_t)(b * NS + s0)) * ND + d;
    float acc = 0.f;
    #pragma unroll 8
    for (int s = 0; s < 256; s++) acc += ws[s] * __half2float(kp[(size_t)s * ND]);
    g_ctx_part[z][b * ND + d] = acc;
}

// ---------------- Kernel 4: reduce context partials -> output ----------------
__global__ void ctx_reduce_kernel(float* __restrict__ ctx) {
    int b = blockIdx.x;
    int d = threadIdx.x;                      // 1024 threads
    float a = 0.f;
    #pragma unroll
    for (int z = 0; z < 8; z++) a += g_ctx_part[z][b * ND + d];
    ctx[b * ND + d] = a;
}

// ---------------- launch ----------------
extern "C" void kernel_launch(void* const* d_in, const int* in_sizes, int n_in,
                              void* d_out, int out_size) {
    const float* query = (const float*)d_in[0];
    const float* keys  = (const float*)d_in[1];
    const float* Wa_w  = (const float*)d_in[2];
    const float* Wa_b  = (const float*)d_in[3];
    const float* Ua_w  = (const float*)d_in[4];
    const float* Ua_b  = (const float*)d_in[5];
    const float* Va_w  = (const float*)d_in[6];
    // Va_b (d_in[7]) cancels in softmax; scores are not an output.

    float* out = (float*)d_out;
    float* ctx = out;                                  // (B,1,2H) = 32768 floats
    float* wts = (out_size >= NB * ND + NB * NS) ? out + NB * ND : out;  // (B,1,S)

    uint4* keys_h4;  cudaGetSymbolAddress((void**)&keys_h4, g_keys_h4);
    uint4* ua_h4;    cudaGetSymbolAddress((void**)&ua_h4, g_ua_h4);

    cudaFuncSetAttribute(gemm_score_kernel, cudaFuncAttributeMaxDynamicSharedMemorySize, SMEM_BYTES);

    cvt_kernel<<<(size_t)BSR * ND / 8 / 256, 256>>>((const float4*)keys, keys_h4);
    cvt_kernel<<<ND * ND / 8 / 256, 256>>>((const float4*)Ua_w, ua_h4);
    qw_kernel<<<dim3(NB, 8), 128>>>(query, Wa_w, Wa_b, Ua_b);
    gemm_score_kernel<<<dim3(NT_N, BSR / T_M), 128, SMEM_BYTES>>>(Va_w);
    softmax_kernel<<<NB, 256>>>(wts);
    ctx_part_kernel<<<dim3(NB, 8, 8), 128>>>(wts);
    ctx_reduce_kernel<<<NB, 1024>>>(ctx);
}

// round 13
// speedup vs baseline: 1.3257x; 1.0086x over previous
#include <cuda_runtime.h>
#include <cuda_fp16.h>
#include <cstdint>
#include <math.h>

// Problem constants
#define NB   32
#define NS   2048
#define ND   1024
#define BSR  65536      // NB*NS rows
#define T_M  128
#define T_N  128
#define T_K  32
#define NKT  32         // ND / T_K
#define NT_N 8          // 1024 / 128 N-tiles

// Device scratch (no dynamic allocation allowed)
__device__ float g_qw[NB * ND];
__device__ float g_scores_part[NT_N][BSR];
__device__ float g_ctx_part[8][NB * ND];
__device__ uint4 g_keys_h4[(size_t)BSR * ND / 8];   // keys as fp16, 128 MB
__device__ uint4 g_ua_h4[ND * ND / 8];              // Ua_w as fp16, 2 MB

// ---------------- smem layout for gemm kernel (bytes) ----------------
// Per stage: 4 private A stripes (4KB each, wid-indexed) + 2 shared B stripes
// (4KB each, wn-indexed) = 24KB. 64B rows, XOR chunk swizzle.
#define STG_BYTES 24576
#define NSTAGE   3
#define OFF_QW   (NSTAGE * STG_BYTES)      // 73728: 128 floats
#define OFF_VA   (OFF_QW + 512)
#define OFF_SC   (OFF_VA + 512)            // 256 floats
#define SMEM_BYTES (OFF_SC + 1024)         // 75776

__device__ __forceinline__ void mma_f16(float* d, const uint32_t* a, const uint32_t* b) {
    asm volatile(
        "mma.sync.aligned.m16n8k16.row.col.f32.f16.f16.f32 "
        "{%0,%1,%2,%3}, {%4,%5,%6,%7}, {%8,%9}, {%0,%1,%2,%3};"
        : "+f"(d[0]), "+f"(d[1]), "+f"(d[2]), "+f"(d[3])
        : "r"(a[0]), "r"(a[1]), "r"(a[2]), "r"(a[3]), "r"(b[0]), "r"(b[1]));
}

__device__ __forceinline__ void ldsm_x4(uint32_t* r, uint32_t addr) {
    asm volatile("ldmatrix.sync.aligned.m8n8.x4.shared.b16 {%0,%1,%2,%3}, [%4];"
        : "=r"(r[0]), "=r"(r[1]), "=r"(r[2]), "=r"(r[3]) : "r"(addr));
}

__device__ __forceinline__ uint32_t pack2h(float x, float y) {
    __half2 h = __floats2half2_rn(x, y);
    return *(uint32_t*)&h;
}

// ---------------- Kernel A: fp32 -> fp16 converters ----------------
__global__ void cvt_kernel(const float4* __restrict__ src, uint4* __restrict__ dst) {
    size_t i = (size_t)blockIdx.x * blockDim.x + threadIdx.x;   // one uint4 = 8 halves
    float4 a = src[2 * i];
    float4 b = src[2 * i + 1];
    uint4 u;
    u.x = pack2h(a.x, a.y);
    u.y = pack2h(a.z, a.w);
    u.z = pack2h(b.x, b.y);
    u.w = pack2h(b.z, b.w);
    dst[i] = u;
}

// ---------------- Kernel 0: qW[b,n] = q[b] . Wa_w[n,:] + Wa_b[n] + Ua_b[n] ----------------
__global__ void qw_kernel(const float* __restrict__ query, const float* __restrict__ Wa_w,
                          const float* __restrict__ Wa_b, const float* __restrict__ Ua_b) {
    int b = blockIdx.x;
    int tid = threadIdx.x;                    // 128 threads
    int n = blockIdx.y * 128 + tid;
    __shared__ float4 qs[256];                // q[b] as 1024 floats
    for (int i = tid; i < 256; i += 128) {
        int k = i * 4;
        // q = concat(query[b,1,:], query[b,3,:]); query is (B,4,512)
        const float* src = (k < 512) ? (query + (size_t)b * 2048 + 512 + k)
                                     : (query + (size_t)b * 2048 + 1024 + k);
        qs[i] = *(const float4*)src;
    }
    __syncthreads();
    const float4* wr = (const float4*)(Wa_w + (size_t)n * ND);
    float acc = 0.f;
    #pragma unroll 8
    for (int i = 0; i < 256; i++) {
        float4 a = qs[i], w = wr[i];
        acc += a.x * w.x + a.y * w.y + a.z * w.z + a.w * w.w;
    }
    g_qw[b * ND + n] = acc + Wa_b[n] + Ua_b[n];
}

// ---------------- Kernel 1: fp16 mma GEMM, warp-autonomous + pair-shared B ----------------
// 128x128 CTA, 4 warps of 64x64, 2 CTA/SM. Each warp loads its own A stripe and
// HALF of the B stripe shared with its pair partner (same wn). One named
// bar.sync(1+wn, 64) per tile; no CTA-wide barriers in the mainloop.
__global__ void __launch_bounds__(128, 2)
gemm_score_kernel(const float* __restrict__ Va_w) {
    extern __shared__ __align__(16) char smc[];
    float* qw_s = (float*)(smc + OFF_QW);
    float* va_s = (float*)(smc + OFF_VA);
    float* sc_s = (float*)(smc + OFF_SC);

    const __half* keys_h = (const __half*)g_keys_h4;
    const __half* ua_h   = (const __half*)g_ua_h4;

    const int tid = threadIdx.x;              // 128 threads, 4 warps
    const int wid = tid >> 5;
    const int lane = tid & 31;
    const int r = lane >> 2;                  // 0..7
    const int c = lane & 3;                   // 0..3
    const int wm = wid & 1;                   // 2 warps along M (64 rows each)
    const int wn = wid >> 1;                  // 2 warps along N (64 cols each)

    const int nt = blockIdx.x;                // N-tile (fast dim -> A reuse in L2)
    const int n0 = nt * T_N;
    const int m0 = blockIdx.y * T_M;
    const int b  = blockIdx.y >> 4;           // 16 M-tiles of 128 per batch

    const uint32_t sbase = (uint32_t)__cvta_generic_to_shared(smc);

    // global stripe bases
    const __half* agl = keys_h + (size_t)(m0 + wm * 64) * ND;       // private A
    const __half* bgl = ua_h + (size_t)(n0 + wn * 64) * ND;         // shared-B stripe

    // loader: A = 256 chunks (8/lane), B-half = 128 chunks (4/lane), 16B each
    // chunk j: row = j>>2, c0 = j&3; smem chunk = c0 ^ ((row>>1)&3)
    auto load_tile = [&](int kt, int s) {
        uint32_t stg = sbase + s * STG_BYTES;
        uint32_t wa = stg + wid * 4096;                    // private A stripe
        uint32_t wbv = stg + 16384 + wn * 4096;            // shared B stripe
        const __half* asrc = agl + (size_t)kt * T_K;
        const __half* bsrc = bgl + (size_t)kt * T_K;
        #pragma unroll
        for (int i = 0; i < 8; i++) {
            int j = lane + i * 32;
            int row = j >> 2, c0 = j & 3;
            int ch = c0 ^ ((row >> 1) & 3);
            asm volatile("cp.async.cg.shared.global [%0], [%1], 16;"
                :: "r"(wa + (uint32_t)(row * 64 + ch * 16)),
                   "l"(asrc + (size_t)row * ND + c0 * 8));
        }
        #pragma unroll
        for (int i = 0; i < 4; i++) {
            int j = lane + i * 32;
            int rl = (j >> 2) + wm * 32, c0 = j & 3;       // this warp's half rows
            int ch = c0 ^ ((rl >> 1) & 3);
            asm volatile("cp.async.cg.shared.global [%0], [%1], 16;"
                :: "r"(wbv + (uint32_t)(rl * 64 + ch * 16)),
                   "l"(bsrc + (size_t)rl * ND + c0 * 8));
        }
        asm volatile("cp.async.commit_group;");
    };

    // ldmatrix lane geometry (A): lanes 0-15 -> rows 0-15, lanes 16-31 -> k+16B
    const int frow_a = lane & 15;
    const int kh_a   = lane >> 4;
    const int sw_a   = (frow_a >> 1) & 3;
    // ldmatrix lane geometry (B): {0-7,8-15,16-23,24-31} -> {n0-7/k0, n0-7/k1, n8-15/k0, n8-15/k1}
    const int frow_b = ((lane >> 4) << 3) + (lane & 7);
    const int kh_b   = (lane >> 3) & 1;
    const int sw_b   = (frow_b >> 1) & 3;

    for (int j = tid; j < T_N; j += 128) {
        qw_s[j] = g_qw[b * ND + n0 + j];
        va_s[j] = Va_w[n0 + j];
    }
    __syncthreads();                          // qw/va visible before any warp's epilogue

    load_tile(0, 0);
    load_tile(1, 1);
    load_tile(2, 2);

    float acc[4][8][4];
    #pragma unroll
    for (int im = 0; im < 4; im++)
        #pragma unroll
        for (int in = 0; in < 8; in++)
            #pragma unroll
            for (int k = 0; k < 4; k++) acc[im][in][k] = 0.f;

    for (int kt = 0; kt < NKT; kt++) {
        const int s = kt % NSTAGE;
        // tiles kt and kt+1 landed (partner's B(kt) visibility: partner waited
        // for kt at its tile kt-1 top, then both crossed bar_b(kt-1))
        if (kt + 1 < NKT) { asm volatile("cp.async.wait_group 1;"); }
        else              { asm volatile("cp.async.wait_group 0;"); }
        __syncwarp();

        const uint32_t stg = sbase + s * STG_BYTES;
        const uint32_t wa = stg + wid * 4096;
        const uint32_t wbv = stg + 16384 + wn * 4096;

        // ---- ks = 0: LDSM + MMA ----
        uint32_t afr[4][4], bfr[4][4];
        #pragma unroll
        for (int im = 0; im < 4; im++)
            ldsm_x4(afr[im], wa + (uint32_t)((im * 16 + frow_a) * 64 + (kh_a ^ sw_a) * 16));
        #pragma unroll
        for (int ip = 0; ip < 4; ip++)
            ldsm_x4(bfr[ip], wbv + (uint32_t)((ip * 16 + frow_b) * 64 + (kh_b ^ sw_b) * 16));
        #pragma unroll
        for (int in = 0; in < 8; in++) {
            const uint32_t* bb = &bfr[in >> 1][(in & 1) * 2];
            #pragma unroll
            for (int im = 0; im < 4; im++)
                mma_f16(acc[im][in], afr[im], bb);
        }

        // ---- ks = 1: LDSM, then pair barrier, then reload stage, then MMA ----
        uint32_t afr2[4][4], bfr2[4][4];
        #pragma unroll
        for (int im = 0; im < 4; im++)
            ldsm_x4(afr2[im], wa + (uint32_t)((im * 16 + frow_a) * 64 + ((2 + kh_a) ^ sw_a) * 16));
        #pragma unroll
        for (int ip = 0; ip < 4; ip++)
            ldsm_x4(bfr2[ip], wbv + (uint32_t)((ip * 16 + frow_b) * 64 + ((2 + kh_b) ^ sw_b) * 16));

        // pair barrier: both partners done reading stage s; safe to overwrite
        asm volatile("bar.sync %0, %1;" :: "r"(1 + wn), "r"(64) : "memory");
        if (kt + 3 < NKT)
            load_tile(kt + 3, s);

        #pragma unroll
        for (int in = 0; in < 8; in++) {
            const uint32_t* bb = &bfr2[in >> 1][(in & 1) * 2];
            #pragma unroll
            for (int im = 0; im < 4; im++)
                mma_f16(acc[im][in], afr2[im], bb);
        }
    }

    // Epilogue: score_part[m] = sum_n Va[n] * tanh(acc[m][n] + qw[n]) over this CTA's 128 n
    #pragma unroll
    for (int im = 0; im < 4; im++) {
        float rs0 = 0.f, rs1 = 0.f;
        #pragma unroll
        for (int in = 0; in < 8; in++) {
            int col0 = wn * 64 + in * 8 + 2 * c;
            float v0 = va_s[col0],     q0 = qw_s[col0];
            float v1 = va_s[col0 + 1], q1 = qw_s[col0 + 1];
            rs0 += v0 * tanhf(acc[im][in][0] + q0) + v1 * tanhf(acc[im][in][1] + q1);
            rs1 += v0 * tanhf(acc[im][in][2] + q0) + v1 * tanhf(acc[im][in][3] + q1);
        }
        // reduce the 4 lanes sharing each row (lane^1, lane^2 stay in the quad)
        rs0 += __shfl_xor_sync(0xffffffffu, rs0, 1);
        rs0 += __shfl_xor_sync(0xffffffffu, rs0, 2);
        rs1 += __shfl_xor_sync(0xffffffffu, rs1, 1);
        rs1 += __shfl_xor_sync(0xffffffffu, rs1, 2);
        if (c == 0) {
            int rowb = wm * 64 + im * 16 + r;
            sc_s[wn * 128 + rowb] = rs0;
            sc_s[wn * 128 + rowb + 8] = rs1;
        }
    }
    __syncthreads();
    g_scores_part[nt][m0 + tid] = sc_s[tid] + sc_s[128 + tid];
}

// ---------------- Kernel 2: softmax over S per batch, writes weights output ----------------
__global__ void softmax_kernel(float* __restrict__ wts) {
    int b = blockIdx.x;
    int tid = threadIdx.x;                    // 256 threads
    __shared__ float red[8];
    float v[8];
    float mx = -1e30f;
    #pragma unroll
    for (int i = 0; i < 8; i++) {
        int s = tid + i * 256;
        float x = 0.f;
        #pragma unroll
        for (int t = 0; t < NT_N; t++) x += g_scores_part[t][b * NS + s];
        v[i] = x;
        mx = fmaxf(mx, x);
    }
    #pragma unroll
    for (int o = 16; o; o >>= 1) mx = fmaxf(mx, __shfl_xor_sync(0xffffffffu, mx, o));
    if ((tid & 31) == 0) red[tid >> 5] = mx;
    __syncthreads();
    float bm = red[0];
    #pragma unroll
    for (int i = 1; i < 8; i++) bm = fmaxf(bm, red[i]);
    __syncthreads();
    float sum = 0.f;
    #pragma unroll
    for (int i = 0; i < 8; i++) { v[i] = __expf(v[i] - bm); sum += v[i]; }
    #pragma unroll
    for (int o = 16; o; o >>= 1) sum += __shfl_xor_sync(0xffffffffu, sum, o);
    if ((tid & 31) == 0) red[tid >> 5] = sum;
    __syncthreads();
    float bs = 0.f;
    #pragma unroll
    for (int i = 0; i < 8; i++) bs += red[i];
    float inv = 1.0f / bs;
    #pragma unroll
    for (int i = 0; i < 8; i++) wts[b * NS + tid + i * 256] = v[i] * inv;
}

// ---------------- Kernel 3: context partials from fp16 keys (halved traffic) ----------------
__global__ void ctx_part_kernel(const float* __restrict__ wts) {
    const __half* keys_h = (const __half*)g_keys_h4;
    int b = blockIdx.x;
    int d = blockIdx.y * 128 + threadIdx.x;
    int z = blockIdx.z;
    int s0 = z * 256;
    __shared__ float ws[256];
    for (int i = threadIdx.x; i < 256; i += 128) ws[i] = wts[b * NS + s0 + i];
    __syncthreads();
    const __half* kp = keys_h + ((size_t)(b * NS + s0)) * ND + d;
    float acc = 0.f;
    #pragma unroll 8
    for (int s = 0; s < 256; s++) acc += ws[s] * __half2float(kp[(size_t)s * ND]);
    g_ctx_part[z][b * ND + d] = acc;
}

// ---------------- Kernel 4: reduce context partials -> output ----------------
__global__ void ctx_reduce_kernel(float* __restrict__ ctx) {
    int b = blockIdx.x;
    int d = threadIdx.x;                      // 1024 threads
    float a = 0.f;
    #pragma unroll
    for (int z = 0; z < 8; z++) a += g_ctx_part[z][b * ND + d];
    ctx[b * ND + d] = a;
}

// ---------------- launch ----------------
extern "C" void kernel_launch(void* const* d_in, const int* in_sizes, int n_in,
                              void* d_out, int out_size) {
    const float* query = (const float*)d_in[0];
    const float* keys  = (const float*)d_in[1];
    const float* Wa_w  = (const float*)d_in[2];
    const float* Wa_b  = (const float*)d_in[3];
    const float* Ua_w  = (const float*)d_in[4];
    const float* Ua_b  = (const float*)d_in[5];
    const float* Va_w  = (const float*)d_in[6];
    // Va_b (d_in[7]) cancels in softmax; scores are not an output.

    float* out = (float*)d_out;
    float* ctx = out;                                  // (B,1,2H) = 32768 floats
    float* wts = (out_size >= NB * ND + NB * NS) ? out + NB * ND : out;  // (B,1,S)

    uint4* keys_h4;  cudaGetSymbolAddress((void**)&keys_h4, g_keys_h4);
    uint4* ua_h4;    cudaGetSymbolAddress((void**)&ua_h4, g_ua_h4);

    cudaFuncSetAttribute(gemm_score_kernel, cudaFuncAttributeMaxDynamicSharedMemorySize, SMEM_BYTES);

    cvt_kernel<<<(size_t)BSR * ND / 8 / 256, 256>>>((const float4*)keys, keys_h4);
    cvt_kernel<<<ND * ND / 8 / 256, 256>>>((const float4*)Ua_w, ua_h4);
    qw_kernel<<<dim3(NB, 8), 128>>>(query, Wa_w, Wa_b, Ua_b);
    gemm_score_kernel<<<dim3(NT_N, BSR / T_M), 128, SMEM_BYTES>>>(Va_w);
    softmax_kernel<<<NB, 256>>>(wts);
    ctx_part_kernel<<<dim3(NB, 8, 8), 128>>>(wts);
    ctx_reduce_kernel<<<NB, 1024>>>(ctx);
}